// round 6
// baseline (speedup 1.0000x reference)
#include <cuda_runtime.h>
#include <cuda_bf16.h>
#include <math.h>
#include <stdint.h>

// Problem constants
#define B_  4
#define N_  4096
#define D_  1024
#define H_  16
#define DH_ 64
#define M_  (B_ * N_)          // 16384
#define MD_ ((size_t)M_ * D_)
#define DD_ ((size_t)D_ * D_)

// ---------------------------------------------------------------------------
// Scratch (__device__ globals; no allocation allowed)
// ---------------------------------------------------------------------------
__device__ __nv_bfloat16 g_qpl [2 * MD_];      // q input planes   (hi | lo)
__device__ __nv_bfloat16 g_qspl[2 * MD_];      // qs planes        (hi | lo)
__device__ __nv_bfloat16 g_xkT [2 * MD_];      // Xk^T  [b][c][n]  (hi | lo)
__device__ __nv_bfloat16 g_xvT [2 * MD_];      // Xv^T  [b][c][n]  (hi | lo)
__device__ __nv_bfloat16 g_gpl [2 * 4 * DD_];  // G'[b][c'][c]     (hi | lo)
__device__ __nv_bfloat16 g_wpl [4 * DD_];      // Wq hi, Wq lo, Wk hi, Wk lo
__device__ __nv_bfloat16 g_vtpl[2 * 4 * DD_];  // Vt[b][r][hd]     (hi | lo)
__device__ float g_P[4 * DD_];                 // P[b][hd][c']
__device__ float g_ctxm[(size_t)64 * 64 * 64]; // ctx[bh][d][e]
__device__ float g_sk[4 * 1024], g_sv[4 * 1024];
__device__ float g_u [4 * 1024], g_w [4 * 1024];

// ---------------------------------------------------------------------------
// PTX helpers (plain sm_103-safe: ldmatrix / mma.sync / cp.async only)
// ---------------------------------------------------------------------------
__device__ __forceinline__ uint32_t smem_u32(const void* p) {
    uint32_t a;
    asm("{ .reg .u64 t; cvta.to.shared.u64 t, %1; cvt.u32.u64 %0, t; }"
        : "=r"(a) : "l"(p));
    return a;
}

#define CPA16(dst, src) \
    asm volatile("cp.async.cg.shared.global [%0], [%1], 16;" :: "r"(dst), "l"(src))
#define CPCOMMIT() asm volatile("cp.async.commit_group;" ::: "memory")
#define CPWAIT2()  asm volatile("cp.async.wait_group 2;" ::: "memory")

#define LDSM4(r, addr) \
    asm volatile("ldmatrix.sync.aligned.m8n8.x4.shared.b16 {%0,%1,%2,%3}, [%4];" \
        : "=r"((r)[0]), "=r"((r)[1]), "=r"((r)[2]), "=r"((r)[3]) : "r"(addr))

#define MMA16816(acc, a, b0, b1) \
    asm volatile("mma.sync.aligned.m16n8k16.row.col.f32.bf16.bf16.f32 " \
        "{%0,%1,%2,%3}, {%4,%5,%6,%7}, {%8,%9}, {%0,%1,%2,%3};" \
        : "+f"((acc)[0]), "+f"((acc)[1]), "+f"((acc)[2]), "+f"((acc)[3]) \
        : "r"((a)[0]), "r"((a)[1]), "r"((a)[2]), "r"((a)[3]), "r"(b0), "r"(b1))

__device__ __forceinline__ void split1(float x, uint16_t& h, uint16_t& l) {
    __nv_bfloat16 hb = __float2bfloat16(x);
    __nv_bfloat16 lb = __float2bfloat16(x - __bfloat162float(hb));
    h = __bfloat16_as_ushort(hb);
    l = __bfloat16_as_ushort(lb);
}

// ---------------------------------------------------------------------------
// Row-major split: fp32 -> hi/lo bf16 planes
// ---------------------------------------------------------------------------
__global__ __launch_bounds__(256)
void split_kernel(const float* __restrict__ in,
                  __nv_bfloat16* __restrict__ hi,
                  __nv_bfloat16* __restrict__ lo, int n4)
{
    int i = blockIdx.x * blockDim.x + threadIdx.x;
    int stride = gridDim.x * blockDim.x;
    for (; i < n4; i += stride) {
        float4 v = ((const float4*)in)[i];
        uint16_t h0,l0,h1,l1,h2,l2,h3,l3;
        split1(v.x,h0,l0); split1(v.y,h1,l1); split1(v.z,h2,l2); split1(v.w,h3,l3);
        uint2 hv, lv;
        hv.x = (uint32_t)h0 | ((uint32_t)h1 << 16);
        hv.y = (uint32_t)h2 | ((uint32_t)h3 << 16);
        lv.x = (uint32_t)l0 | ((uint32_t)l1 << 16);
        lv.y = (uint32_t)l2 | ((uint32_t)l3 << 16);
        *(uint2*)(hi + 4 * (size_t)i) = hv;
        *(uint2*)(lo + 4 * (size_t)i) = lv;
    }
}

// ---------------------------------------------------------------------------
// Transposing split + fused column sum:
// x[b][n][c] fp32 -> planes [b][c][n] bf16 (hi, lo); s[b][c] += sum_n x
// ---------------------------------------------------------------------------
__global__ __launch_bounds__(256)
void splitT_kernel(const float* __restrict__ in,
                   __nv_bfloat16* __restrict__ hi,
                   __nv_bfloat16* __restrict__ lo,
                   float* __restrict__ s)
{
    __shared__ float t[32][33];
    const int n0 = blockIdx.x * 32;
    const int c0 = blockIdx.y * 32;
    const int b  = blockIdx.z;

    {
        int row = threadIdx.x >> 3;          // n-local
        int c4  = (threadIdx.x & 7) * 4;     // c-local
        float4 v = *(const float4*)(in + ((size_t)b * N_ + n0 + row) * D_ + c0 + c4);
        t[c4 + 0][row] = v.x; t[c4 + 1][row] = v.y;
        t[c4 + 2][row] = v.z; t[c4 + 3][row] = v.w;
    }
    __syncthreads();
    {
        int c  = threadIdx.x >> 3;           // c-local
        int n4 = (threadIdx.x & 7) * 4;      // n-local
        float v0 = t[c][n4 + 0], v1 = t[c][n4 + 1];
        float v2 = t[c][n4 + 2], v3 = t[c][n4 + 3];

        float sum = (v0 + v1) + (v2 + v3);
        sum += __shfl_xor_sync(0xffffffffu, sum, 1);
        sum += __shfl_xor_sync(0xffffffffu, sum, 2);
        sum += __shfl_xor_sync(0xffffffffu, sum, 4);
        if ((threadIdx.x & 7) == 0)
            atomicAdd(&s[b * D_ + c0 + c], sum);

        uint16_t h0,l0,h1,l1,h2,l2,h3,l3;
        split1(v0, h0, l0); split1(v1, h1, l1);
        split1(v2, h2, l2); split1(v3, h3, l3);
        uint2 hv, lv;
        hv.x = (uint32_t)h0 | ((uint32_t)h1 << 16);
        hv.y = (uint32_t)h2 | ((uint32_t)h3 << 16);
        lv.x = (uint32_t)l0 | ((uint32_t)l1 << 16);
        lv.y = (uint32_t)l2 | ((uint32_t)l3 << 16);
        size_t off = ((size_t)b * D_ + c0 + c) * N_ + n0 + n4;
        *(uint2*)(hi + off) = hv;
        *(uint2*)(lo + off) = lv;
    }
}

// u[b][r] = sum_c W[r][c] * s[b][c]
__global__ __launch_bounds__(256)
void matvec_k(const float* __restrict__ W, const float* __restrict__ s,
              float* __restrict__ u)
{
    const int b = blockIdx.x;
    const int r = blockIdx.y * 8 + (threadIdx.x >> 5);
    const int lane = threadIdx.x & 31;
    float sum = 0.f;
    for (int c = lane; c < D_; c += 32)
        sum += W[(size_t)r * D_ + c] * s[b * D_ + c];
#pragma unroll
    for (int off = 16; off > 0; off >>= 1)
        sum += __shfl_xor_sync(0xffffffffu, sum, off);
    if (lane == 0) u[b * D_ + r] = sum;
}

// ---------------------------------------------------------------------------
// bf16x3 mma.sync GEMM, CTA tile 256x128, 512 threads (16 warps), warp tile
// 32x64, BK=32, 3-stage cp.async pipeline.
// C[i,j] = sum_k (Ah+Al)[i,k]*(Bh+Bl)[j,k].
// Output fp32 OR bf16 hi/lo planes. Optional fused bias + 64-chunk softmax.
// ---------------------------------------------------------------------------
#define BM 256
#define BN 128
#define BK 32
#define NTHREADS 512
#define TA_BYTES (BM * 64)                       // 16384
#define TB_BYTES (BN * 64)                       // 8192
#define STG_BYTES (2 * TA_BYTES + 2 * TB_BYTES)  // 49152
#define NPIPE 3
#define GSMEM (NPIPE * STG_BYTES)                // 147456

__device__ __forceinline__ uint32_t swz(uint32_t row, uint32_t c) {
    return row * 64u + ((c ^ ((row >> 1) & 3u)) << 4);
}

__global__ __launch_bounds__(NTHREADS, 1)
void mma_gemm(const __nv_bfloat16* __restrict__ aHi,
              const __nv_bfloat16* __restrict__ bHi,
              const float* __restrict__ bias,
              float* __restrict__ cF32,
              __nv_bfloat16* __restrict__ cHi,
              int Kdim, int ldc,
              size_t aPS, size_t bPS, size_t cPS,   // hi->lo plane strides
              size_t aStride, size_t bStride, size_t cStride,  // batch strides
              int do_softmax, float scale)
{
    extern __shared__ char smem[];
    const uint32_t sbase = smem_u32(smem);
    const int tid  = threadIdx.x;
    const int wid  = tid >> 5;
    const int lane = tid & 31;
    const int warp_m = wid & 7;          // 8 warps over M (32 rows each)
    const int warp_n = wid >> 3;         // 2 warps over N (64 cols each)
    const int rowBase = blockIdx.y * BM;
    const int colBase = blockIdx.x * BN;
    const int z = blockIdx.z;

    aHi += (size_t)z * aStride;
    bHi += (size_t)z * bStride;

    // ---- loader setup: 4 A-chunks + 2 B-chunks per thread per stage -----
    uint32_t goffA[4], sdstA[4];
    uint32_t goffB[2], sdstB[2];
#pragma unroll
    for (int i = 0; i < 4; ++i) {
        int q = i * NTHREADS + tid;      // 0..2047
        int plane = q >> 10;             // 1024 chunks per plane (256 rows x 4)
        int w = q & 1023;
        int row = w >> 2, c = w & 3;
        goffA[i] = (uint32_t)(plane * aPS + (size_t)(rowBase + row) * Kdim + c * 8);
        sdstA[i] = (uint32_t)(plane * TA_BYTES) + swz((uint32_t)row, (uint32_t)c);
    }
#pragma unroll
    for (int i = 0; i < 2; ++i) {
        int q = i * NTHREADS + tid;      // 0..1023
        int plane = q >> 9;              // 512 chunks per plane (128 rows x 4)
        int w = q & 511;
        int row = w >> 2, c = w & 3;
        goffB[i] = (uint32_t)(plane * bPS + (size_t)(colBase + row) * Kdim + c * 8);
        sdstB[i] = (uint32_t)(2 * TA_BYTES + plane * TB_BYTES) + swz((uint32_t)row, (uint32_t)c);
    }

    const int nstage = Kdim / BK;

    // prologue: stages 0 and 1
#pragma unroll
    for (int s = 0; s < 2; ++s) {
        uint32_t sb = sbase + s * STG_BYTES;
        const int koff = s * BK;
#pragma unroll
        for (int i = 0; i < 4; ++i) CPA16(sb + sdstA[i], aHi + goffA[i] + koff);
#pragma unroll
        for (int i = 0; i < 2; ++i) CPA16(sb + sdstB[i], bHi + goffB[i] + koff);
        CPCOMMIT();
    }

    // ---- fragment smem offsets (within a plane-tile) --------------------
    uint32_t aoff[2][2], boff[4][2];
#pragma unroll
    for (int m = 0; m < 2; ++m) {
        uint32_t arow = warp_m * 32 + m * 16 + (lane & 7) + ((lane >> 3) & 1) * 8;
#pragma unroll
        for (int ks = 0; ks < 2; ++ks)
            aoff[m][ks] = swz(arow, 2 * ks + (lane >> 4));
    }
#pragma unroll
    for (int p = 0; p < 4; ++p) {
        uint32_t brow = warp_n * 64 + p * 16 + (lane & 7) + ((lane >= 16) ? 8 : 0);
#pragma unroll
        for (int ks = 0; ks < 2; ++ks)
            boff[p][ks] = swz(brow, 2 * ks + ((lane >> 3) & 1));
    }

    float acc[2][8][4];
#pragma unroll
    for (int m = 0; m < 2; ++m)
#pragma unroll
        for (int n = 0; n < 8; ++n)
#pragma unroll
            for (int r = 0; r < 4; ++r) acc[m][n][r] = 0.0f;

    int bufc = 0;   // compute buffer
    int bufl = 2;   // load buffer (stage s+2)
    for (int s = 0; s < nstage; ++s) {
        // issue stage s+2 into bufl (its previous tenant s-1 is done+synced)
        if (s + 2 < nstage) {
            uint32_t sb = sbase + bufl * STG_BYTES;
            const int koff = (s + 2) * BK;
#pragma unroll
            for (int i = 0; i < 4; ++i) CPA16(sb + sdstA[i], aHi + goffA[i] + koff);
#pragma unroll
            for (int i = 0; i < 2; ++i) CPA16(sb + sdstB[i], bHi + goffB[i] + koff);
        }
        CPCOMMIT();
        CPWAIT2();            // stage s guaranteed complete
        __syncthreads();

        const uint32_t sb = sbase + bufc * STG_BYTES;
#pragma unroll
        for (int ks = 0; ks < 2; ++ks) {
            uint32_t ah[2][4], al[2][4];
#pragma unroll
            for (int m = 0; m < 2; ++m) {
                LDSM4(ah[m], sb + aoff[m][ks]);
                LDSM4(al[m], sb + TA_BYTES + aoff[m][ks]);
            }
#pragma unroll
            for (int p = 0; p < 4; ++p) {
                uint32_t bh[4], bl[4];
                LDSM4(bh, sb + 2 * TA_BYTES + boff[p][ks]);
                LDSM4(bl, sb + 2 * TA_BYTES + TB_BYTES + boff[p][ks]);
#pragma unroll
                for (int m = 0; m < 2; ++m) {
#pragma unroll
                    for (int q = 0; q < 2; ++q) {
                        float* a4 = acc[m][2 * p + q];
                        MMA16816(a4, ah[m], bh[2 * q], bh[2 * q + 1]);
                        MMA16816(a4, ah[m], bl[2 * q], bl[2 * q + 1]);
                        MMA16816(a4, al[m], bh[2 * q], bh[2 * q + 1]);
                    }
                }
            }
        }
        __syncthreads();      // all warps done with bufc before it is reloaded
        bufc = (bufc + 1) % NPIPE;
        bufl = (bufl + 1) % NPIPE;
    }

    // ---- epilogue -------------------------------------------------------
    const int r0 = rowBase + warp_m * 32 + (lane >> 2);
    const int c0 = colBase + warp_n * 64 + (lane & 3) * 2;

    if (bias) {
#pragma unroll
        for (int n = 0; n < 8; ++n) {
            float2 bv = *(const float2*)(bias + c0 + n * 8);
#pragma unroll
            for (int m = 0; m < 2; ++m) {
                acc[m][n][0] += bv.x; acc[m][n][1] += bv.y;
                acc[m][n][2] += bv.x; acc[m][n][3] += bv.y;
            }
        }
    }
    if (do_softmax) {
#pragma unroll
        for (int m = 0; m < 2; ++m) {
#pragma unroll
            for (int hf = 0; hf < 2; ++hf) {
                float mx = -1e30f;
#pragma unroll
                for (int n = 0; n < 8; ++n)
                    mx = fmaxf(mx, fmaxf(acc[m][n][2 * hf], acc[m][n][2 * hf + 1]));
                mx = fmaxf(mx, __shfl_xor_sync(0xffffffffu, mx, 1));
                mx = fmaxf(mx, __shfl_xor_sync(0xffffffffu, mx, 2));
                float sum = 0.0f;
#pragma unroll
                for (int n = 0; n < 8; ++n) {
                    float e0 = __expf(acc[m][n][2 * hf] - mx);
                    float e1 = __expf(acc[m][n][2 * hf + 1] - mx);
                    acc[m][n][2 * hf] = e0; acc[m][n][2 * hf + 1] = e1;
                    sum += e0 + e1;
                }
                sum += __shfl_xor_sync(0xffffffffu, sum, 1);
                sum += __shfl_xor_sync(0xffffffffu, sum, 2);
                float inv = scale / sum;
#pragma unroll
                for (int n = 0; n < 8; ++n) {
                    acc[m][n][2 * hf] *= inv; acc[m][n][2 * hf + 1] *= inv;
                }
            }
        }
    }

    if (cF32) {
        float* Cb = cF32 + (size_t)z * cStride;
#pragma unroll
        for (int m = 0; m < 2; ++m) {
            const int rA = r0 + m * 16, rB = rA + 8;
#pragma unroll
            for (int n = 0; n < 8; ++n) {
                float2 v01; v01.x = acc[m][n][0]; v01.y = acc[m][n][1];
                float2 v23; v23.x = acc[m][n][2]; v23.y = acc[m][n][3];
                *(float2*)(Cb + (size_t)rA * ldc + c0 + n * 8) = v01;
                *(float2*)(Cb + (size_t)rB * ldc + c0 + n * 8) = v23;
            }
        }
    } else {
        __nv_bfloat16* Hb = cHi + (size_t)z * cStride;
        __nv_bfloat16* Lb = cHi + cPS + (size_t)z * cStride;
#pragma unroll
        for (int m = 0; m < 2; ++m) {
            const int rA = r0 + m * 16, rB = rA + 8;
#pragma unroll
            for (int n = 0; n < 8; ++n) {
                uint16_t h0,l0,h1,l1;
                split1(acc[m][n][0], h0, l0);
                split1(acc[m][n][1], h1, l1);
                *(uint32_t*)(Hb + (size_t)rA * ldc + c0 + n * 8) =
                    (uint32_t)h0 | ((uint32_t)h1 << 16);
                *(uint32_t*)(Lb + (size_t)rA * ldc + c0 + n * 8) =
                    (uint32_t)l0 | ((uint32_t)l1 << 16);
                split1(acc[m][n][2], h0, l0);
                split1(acc[m][n][3], h1, l1);
                *(uint32_t*)(Hb + (size_t)rB * ldc + c0 + n * 8) =
                    (uint32_t)h0 | ((uint32_t)h1 << 16);
                *(uint32_t*)(Lb + (size_t)rB * ldc + c0 + n * 8) =
                    (uint32_t)l0 | ((uint32_t)l1 << 16);
            }
        }
    }
}

// ---------------------------------------------------------------------------
// ctx[bh][d][e] = softmax_d( P[b][h64+d,:]·Wv[h64+e,:] + u_d bv_e + bk_d w_e
//                             + N bk_d bv_e ) * scale
// ---------------------------------------------------------------------------
__global__ __launch_bounds__(256)
void ctx_kernel(const float* __restrict__ P, const float* __restrict__ Wv,
                const float* __restrict__ bk, const float* __restrict__ bv,
                const float* __restrict__ u, const float* __restrict__ w,
                float* __restrict__ ctx, float scale)
{
    __shared__ float Ps[64][33];
    __shared__ float Ws[64][33];
    __shared__ float Cm[64][65];

    const int bh = blockIdx.x;
    const int b  = bh >> 4;
    const int h  = bh & 15;
    const float* Pb  = P  + (size_t)b * DD_ + (size_t)(h * 64) * D_;
    const float* Wvb = Wv + (size_t)(h * 64) * D_;

    const int tid = threadIdx.x;
    const int dt = (tid >> 4) * 4;
    const int et = (tid & 15) * 4;
    const int lrow = tid >> 2;
    const int lc   = (tid & 3) * 8;

    float acc[4][4];
#pragma unroll
    for (int i = 0; i < 4; i++)
#pragma unroll
        for (int j = 0; j < 4; j++) acc[i][j] = 0.0f;

    for (int c0 = 0; c0 < D_; c0 += 32) {
#pragma unroll
        for (int i = 0; i < 8; ++i) {
            Ps[lrow][lc + i] = Pb [(size_t)lrow * D_ + c0 + lc + i];
            Ws[lrow][lc + i] = Wvb[(size_t)lrow * D_ + c0 + lc + i];
        }
        __syncthreads();
#pragma unroll 8
        for (int cc = 0; cc < 32; ++cc) {
            float pd[4], we[4];
#pragma unroll
            for (int i = 0; i < 4; ++i) pd[i] = Ps[dt + i][cc];
#pragma unroll
            for (int j = 0; j < 4; ++j) we[j] = Ws[et + j][cc];
#pragma unroll
            for (int i = 0; i < 4; ++i)
#pragma unroll
                for (int j = 0; j < 4; ++j)
                    acc[i][j] = fmaf(pd[i], we[j], acc[i][j]);
        }
        __syncthreads();
    }

    {
        float bkd[4], ud[4], bve[4], wze[4];
#pragma unroll
        for (int i = 0; i < 4; ++i) {
            bkd[i] = bk[h * 64 + dt + i];
            ud[i]  = u [b * D_ + h * 64 + dt + i];
        }
#pragma unroll
        for (int j = 0; j < 4; ++j) {
            bve[j] = bv[h * 64 + et + j];
            wze[j] = w [b * D_ + h * 64 + et + j];
        }
#pragma unroll
        for (int i = 0; i < 4; ++i)
#pragma unroll
            for (int j = 0; j < 4; ++j)
                acc[i][j] += ud[i] * bve[j] + bkd[i] * wze[j]
                           + (float)N_ * bkd[i] * bve[j];
    }

#pragma unroll
    for (int i = 0; i < 4; i++)
#pragma unroll
        for (int j = 0; j < 4; j++)
            Cm[dt + i][et + j] = acc[i][j];
    __syncthreads();

    if (tid < 64) {
        float m = -1e30f;
#pragma unroll 8
        for (int d = 0; d < 64; d++) m = fmaxf(m, Cm[d][tid]);
        float s = 0.0f;
#pragma unroll 8
        for (int d = 0; d < 64; d++) {
            float e = __expf(Cm[d][tid] - m);
            Cm[d][tid] = e;
            s += e;
        }
        float inv = scale / s;
        float* outp = ctx + (size_t)bh * (DH_ * DH_);
#pragma unroll 8
        for (int d = 0; d < 64; d++)
            outp[d * 64 + tid] = Cm[d][tid] * inv;
    }
}

// ---------------------------------------------------------------------------
// Vt[b][r][h64+d] = sum_e Wo[r][h64+e] * ctx[bh][d][e]  -> bf16 hi/lo planes
// ---------------------------------------------------------------------------
__global__ __launch_bounds__(256)
void vt_kernel(const float* __restrict__ ctx, const float* __restrict__ Wo,
               __nv_bfloat16* __restrict__ vtHi, __nv_bfloat16* __restrict__ vtLo)
{
    __shared__ float Cs[64][65];
    __shared__ float Wos[64][65];

    const int bh = blockIdx.x;
    const int b  = bh >> 4;
    const int h  = bh & 15;
    const int r0 = blockIdx.y * 64;
    const int tid = threadIdx.x;

    {
        int d  = tid >> 2;
        int e0 = (tid & 3) * 16;
        const float* src = ctx + (size_t)bh * 4096 + (size_t)d * 64 + e0;
#pragma unroll
        for (int i = 0; i < 16; ++i) Cs[d][e0 + i] = src[i];
        int lr = tid >> 2;
        int c0 = (tid & 3) * 16;
        const float* ws = Wo + (size_t)(r0 + lr) * D_ + h * 64 + c0;
#pragma unroll
        for (int i = 0; i < 16; ++i) Wos[lr][c0 + i] = ws[i];
    }
    __syncthreads();

    const int rl = tid >> 2;
    const int dq = tid & 3;
    float acc[16];
#pragma unroll
    for (int d = 0; d < 16; ++d) acc[d] = 0.0f;

#pragma unroll 8
    for (int e = 0; e < 64; ++e) {
        float wo = Wos[rl][e];
#pragma unroll
        for (int d = 0; d < 16; ++d)
            acc[d] = fmaf(wo, Cs[dq * 16 + d][e], acc[d]);
    }

    size_t base = ((size_t)(b * D_ + r0 + rl)) * D_ + h * 64 + dq * 16;
#pragma unroll
    for (int d = 0; d < 16; d += 2) {
        uint16_t h0,l0,h1,l1;
        split1(acc[d],     h0, l0);
        split1(acc[d + 1], h1, l1);
        *(uint32_t*)(vtHi + base + d) = (uint32_t)h0 | ((uint32_t)h1 << 16);
        *(uint32_t*)(vtLo + base + d) = (uint32_t)l0 | ((uint32_t)l1 << 16);
    }
}

// ---------------------------------------------------------------------------
// Launch
// ---------------------------------------------------------------------------
extern "C" void kernel_launch(void* const* d_in, const int* in_sizes, int n_in,
                              void* d_out, int out_size)
{
    const float* q  = (const float*)d_in[0];
    const float* k  = (const float*)d_in[1];
    const float* v  = (const float*)d_in[2];
    const float* Wq = (const float*)d_in[3];
    const float* bq = (const float*)d_in[4];
    const float* Wk = (const float*)d_in[5];
    const float* bk = (const float*)d_in[6];
    const float* Wv = (const float*)d_in[7];
    const float* bv = (const float*)d_in[8];
    const float* Wo = (const float*)d_in[9];
    float* out = (float*)d_out;

    void *p_qpl, *p_qspl, *p_xkT, *p_xvT, *p_gpl, *p_wpl, *p_vtpl,
         *p_P, *p_ctx, *p_sk, *p_sv, *p_u, *p_w;
    cudaGetSymbolAddress(&p_qpl,  g_qpl);
    cudaGetSymbolAddress(&p_qspl, g_qspl);
    cudaGetSymbolAddress(&p_xkT,  g_xkT);
    cudaGetSymbolAddress(&p_xvT,  g_xvT);
    cudaGetSymbolAddress(&p_gpl,  g_gpl);
    cudaGetSymbolAddress(&p_wpl,  g_wpl);
    cudaGetSymbolAddress(&p_vtpl, g_vtpl);
    cudaGetSymbolAddress(&p_P,    g_P);
    cudaGetSymbolAddress(&p_ctx,  g_ctxm);
    cudaGetSymbolAddress(&p_sk,   g_sk);
    cudaGetSymbolAddress(&p_sv,   g_sv);
    cudaGetSymbolAddress(&p_u,    g_u);
    cudaGetSymbolAddress(&p_w,    g_w);
    __nv_bfloat16* qpl  = (__nv_bfloat16*)p_qpl;
    __nv_bfloat16* qspl = (__nv_bfloat16*)p_qspl;
    __nv_bfloat16* xkT  = (__nv_bfloat16*)p_xkT;
    __nv_bfloat16* xvT  = (__nv_bfloat16*)p_xvT;
    __nv_bfloat16* gpl  = (__nv_bfloat16*)p_gpl;
    __nv_bfloat16* wpl  = (__nv_bfloat16*)p_wpl;
    __nv_bfloat16* vtpl = (__nv_bfloat16*)p_vtpl;
    float* Pm   = (float*)p_P;
    float* ctxm = (float*)p_ctx;
    float* sk   = (float*)p_sk;
    float* sv   = (float*)p_sv;
    float* uu   = (float*)p_u;
    float* ww   = (float*)p_w;

    const float inv_qtr = 0.5946035575013605f;   // 8^(-1/4)

    static int smem_set = 0;
    if (!smem_set) {
        cudaFuncSetAttribute(mma_gemm, cudaFuncAttributeMaxDynamicSharedMemorySize, GSMEM);
        smem_set = 1;
    }

    cudaMemsetAsync(sk, 0, 4 * D_ * sizeof(float));
    cudaMemsetAsync(sv, 0, 4 * D_ * sizeof(float));

    // splits (+ fused column sums in splitT)
    split_kernel<<<512, 256>>>(Wq, wpl, wpl + DD_, (int)(DD_ / 4));
    split_kernel<<<512, 256>>>(Wk, wpl + 2 * DD_, wpl + 3 * DD_, (int)(DD_ / 4));
    split_kernel<<<2048, 256>>>(q, qpl, qpl + MD_, (int)(MD_ / 4));
    {
        dim3 tg(N_ / 32, D_ / 32, B_);
        splitT_kernel<<<tg, 256>>>(k, xkT, xkT + MD_, sk);
        splitT_kernel<<<tg, 256>>>(v, xvT, xvT + MD_, sv);
    }
    matvec_k<<<dim3(B_, 128), 256>>>(Wk, sk, uu);
    matvec_k<<<dim3(B_, 128), 256>>>(Wv, sv, ww);

    // Q projection + fused feature softmax -> qs bf16 planes
    mma_gemm<<<dim3(D_ / BN, M_ / BM, 1), NTHREADS, GSMEM>>>(
        qpl, wpl, bq, nullptr, qspl,
        D_, D_, MD_, DD_, MD_, 0, 0, MD_, 1, inv_qtr);

    // Gram: G'[b] = Xv_b^T Xk_b  -> bf16 planes
    mma_gemm<<<dim3(D_ / BN, D_ / BM, B_), NTHREADS, GSMEM>>>(
        xvT, xkT, nullptr, nullptr, gpl,
        N_, D_, MD_, MD_, 4 * DD_,
        (size_t)D_ * N_, (size_t)D_ * N_, DD_, 0, 0.0f);

    // P[b] = Wk (.) G'[b]  -> fp32
    mma_gemm<<<dim3(D_ / BN, D_ / BM, B_), NTHREADS, GSMEM>>>(
        wpl + 2 * DD_, gpl, nullptr, Pm, nullptr,
        D_, D_, DD_, 4 * DD_, 0, 0, DD_, DD_, 0, 0.0f);

    // ctx (per b,h): P·Wv^T + bias terms, softmax over d, * scale
    ctx_kernel<<<B_ * H_, 256>>>(Pm, Wv, bk, bv, uu, ww, ctxm, inv_qtr);

    // Vt planes
    vt_kernel<<<dim3(B_ * H_, 16), 256>>>(ctxm, Wo, vtpl, vtpl + 4 * DD_);

    // out[b] = qs_b (.) Vt_b
    mma_gemm<<<dim3(D_ / BN, N_ / BM, B_), NTHREADS, GSMEM>>>(
        qspl, vtpl, nullptr, out, nullptr,
        D_, D_, MD_, 4 * DD_, 0,
        (size_t)N_ * D_, DD_, (size_t)N_ * D_, 0, 0.0f);
}

// round 7
// speedup vs baseline: 1.0189x; 1.0189x over previous
#include <cuda_runtime.h>
#include <cuda_bf16.h>
#include <math.h>
#include <stdint.h>

// Problem constants
#define B_  4
#define N_  4096
#define D_  1024
#define H_  16
#define DH_ 64
#define M_  (B_ * N_)          // 16384
#define MD_ ((size_t)M_ * D_)
#define DD_ ((size_t)D_ * D_)

// ---------------------------------------------------------------------------
// Scratch (__device__ globals; no allocation allowed)
// ---------------------------------------------------------------------------
__device__ __nv_bfloat16 g_qpl [2 * MD_];      // q input planes   (hi | lo)
__device__ __nv_bfloat16 g_qspl[2 * MD_];      // qs planes        (hi | lo)
__device__ __nv_bfloat16 g_xkT [2 * MD_];      // Xk^T  [b][c][n]  (hi | lo)
__device__ __nv_bfloat16 g_xvT [2 * MD_];      // Xv^T  [b][c][n]  (hi | lo)
__device__ __nv_bfloat16 g_gpl [2 * 4 * DD_];  // G'[b][c'][c]     (hi | lo)
__device__ __nv_bfloat16 g_wpl [4 * DD_];      // Wq hi, Wq lo, Wk hi, Wk lo
__device__ __nv_bfloat16 g_vtpl[2 * 4 * DD_];  // Vt[b][r][hd]     (hi | lo)
__device__ float g_P[4 * DD_];                 // P[b][hd][c']
__device__ float g_ctxm[(size_t)64 * 64 * 64]; // ctx[bh][d][e]
__device__ float g_spk[4 * 16 * 1024], g_spv[4 * 16 * 1024];  // partial col sums
__device__ float g_sk[4 * 1024], g_sv[4 * 1024];
__device__ float g_u [4 * 1024], g_w [4 * 1024];

// ---------------------------------------------------------------------------
// PTX helpers (plain sm_103-safe: ldmatrix / mma.sync / cp.async only)
// ---------------------------------------------------------------------------
__device__ __forceinline__ uint32_t smem_u32(const void* p) {
    uint32_t a;
    asm("{ .reg .u64 t; cvta.to.shared.u64 t, %1; cvt.u32.u64 %0, t; }"
        : "=r"(a) : "l"(p));
    return a;
}

#define CPA16(dst, src) \
    asm volatile("cp.async.cg.shared.global [%0], [%1], 16;" :: "r"(dst), "l"(src))
#define CPCOMMIT() asm volatile("cp.async.commit_group;" ::: "memory")
#define CPWAIT2()  asm volatile("cp.async.wait_group 2;" ::: "memory")

#define LDSM4(r, addr) \
    asm volatile("ldmatrix.sync.aligned.m8n8.x4.shared.b16 {%0,%1,%2,%3}, [%4];" \
        : "=r"((r)[0]), "=r"((r)[1]), "=r"((r)[2]), "=r"((r)[3]) : "r"(addr))

#define MMA16816(acc, a, b0, b1) \
    asm volatile("mma.sync.aligned.m16n8k16.row.col.f32.bf16.bf16.f32 " \
        "{%0,%1,%2,%3}, {%4,%5,%6,%7}, {%8,%9}, {%0,%1,%2,%3};" \
        : "+f"((acc)[0]), "+f"((acc)[1]), "+f"((acc)[2]), "+f"((acc)[3]) \
        : "r"((a)[0]), "r"((a)[1]), "r"((a)[2]), "r"((a)[3]), "r"(b0), "r"(b1))

__device__ __forceinline__ void split1(float x, uint16_t& h, uint16_t& l) {
    __nv_bfloat16 hb = __float2bfloat16(x);
    __nv_bfloat16 lb = __float2bfloat16(x - __bfloat162float(hb));
    h = __bfloat16_as_ushort(hb);
    l = __bfloat16_as_ushort(lb);
}

// ---------------------------------------------------------------------------
// Row-major split: fp32 -> hi/lo bf16 planes
// ---------------------------------------------------------------------------
__global__ __launch_bounds__(256)
void split_kernel(const float* __restrict__ in,
                  __nv_bfloat16* __restrict__ hi,
                  __nv_bfloat16* __restrict__ lo, int n4)
{
    int i = blockIdx.x * blockDim.x + threadIdx.x;
    int stride = gridDim.x * blockDim.x;
    for (; i < n4; i += stride) {
        float4 v = ((const float4*)in)[i];
        uint16_t h0,l0,h1,l1,h2,l2,h3,l3;
        split1(v.x,h0,l0); split1(v.y,h1,l1); split1(v.z,h2,l2); split1(v.w,h3,l3);
        uint2 hv, lv;
        hv.x = (uint32_t)h0 | ((uint32_t)h1 << 16);
        hv.y = (uint32_t)h2 | ((uint32_t)h3 << 16);
        lv.x = (uint32_t)l0 | ((uint32_t)l1 << 16);
        lv.y = (uint32_t)l2 | ((uint32_t)l3 << 16);
        *(uint2*)(hi + 4 * (size_t)i) = hv;
        *(uint2*)(lo + 4 * (size_t)i) = lv;
    }
}

// ---------------------------------------------------------------------------
// Transposing split: x[b][n][c] fp32 -> planes [b][c][n] bf16 (hi, lo)
// ---------------------------------------------------------------------------
__global__ __launch_bounds__(256)
void splitT_kernel(const float* __restrict__ in,
                   __nv_bfloat16* __restrict__ hi,
                   __nv_bfloat16* __restrict__ lo)
{
    __shared__ float t[32][33];
    const int n0 = blockIdx.x * 32;
    const int c0 = blockIdx.y * 32;
    const int b  = blockIdx.z;

    {
        int row = threadIdx.x >> 3;          // n-local
        int c4  = (threadIdx.x & 7) * 4;     // c-local
        float4 v = *(const float4*)(in + ((size_t)b * N_ + n0 + row) * D_ + c0 + c4);
        t[c4 + 0][row] = v.x; t[c4 + 1][row] = v.y;
        t[c4 + 2][row] = v.z; t[c4 + 3][row] = v.w;
    }
    __syncthreads();
    {
        int c  = threadIdx.x >> 3;           // c-local
        int n4 = (threadIdx.x & 7) * 4;      // n-local
        uint16_t h0,l0,h1,l1,h2,l2,h3,l3;
        split1(t[c][n4 + 0], h0, l0);
        split1(t[c][n4 + 1], h1, l1);
        split1(t[c][n4 + 2], h2, l2);
        split1(t[c][n4 + 3], h3, l3);
        uint2 hv, lv;
        hv.x = (uint32_t)h0 | ((uint32_t)h1 << 16);
        hv.y = (uint32_t)h2 | ((uint32_t)h3 << 16);
        lv.x = (uint32_t)l0 | ((uint32_t)l1 << 16);
        lv.y = (uint32_t)l2 | ((uint32_t)l3 << 16);
        size_t off = ((size_t)b * D_ + c0 + c) * N_ + n0 + n4;
        *(uint2*)(hi + off) = hv;
        *(uint2*)(lo + off) = lv;
    }
}

// ---------------------------------------------------------------------------
// Partial column sums (no atomics): sp[b][sl][c] = sum_{n in slice} x[b][n][c]
// ---------------------------------------------------------------------------
__global__ __launch_bounds__(256)
void colstat_k(const float* __restrict__ x, float* __restrict__ sp)
{
    const int b  = blockIdx.x;
    const int sl = blockIdx.y;
    const int c0 = threadIdx.x * 4;
    float4 a = make_float4(0.f, 0.f, 0.f, 0.f);
    for (int n = sl * 256; n < sl * 256 + 256; ++n) {
        float4 v = *(const float4*)(x + ((size_t)b * N_ + n) * D_ + c0);
        a.x += v.x; a.y += v.y; a.z += v.z; a.w += v.w;
    }
    *(float4*)(sp + ((size_t)(b * 16 + sl)) * D_ + c0) = a;
}

__global__ __launch_bounds__(256)
void sreduce_k(const float* __restrict__ sp, float* __restrict__ s)
{
    const int b  = blockIdx.x;
    const int c0 = threadIdx.x * 4;
    float4 a = make_float4(0.f, 0.f, 0.f, 0.f);
#pragma unroll
    for (int sl = 0; sl < 16; ++sl) {
        float4 v = *(const float4*)(sp + ((size_t)(b * 16 + sl)) * D_ + c0);
        a.x += v.x; a.y += v.y; a.z += v.z; a.w += v.w;
    }
    *(float4*)(s + (size_t)b * D_ + c0) = a;
}

// u[b][r] = sum_c W[r][c] * s[b][c]
__global__ __launch_bounds__(256)
void matvec_k(const float* __restrict__ W, const float* __restrict__ s,
              float* __restrict__ u)
{
    const int b = blockIdx.x;
    const int r = blockIdx.y * 8 + (threadIdx.x >> 5);
    const int lane = threadIdx.x & 31;
    float sum = 0.f;
    for (int c = lane; c < D_; c += 32)
        sum += W[(size_t)r * D_ + c] * s[b * D_ + c];
#pragma unroll
    for (int off = 16; off > 0; off >>= 1)
        sum += __shfl_xor_sync(0xffffffffu, sum, off);
    if (lane == 0) u[b * D_ + r] = sum;
}

// ---------------------------------------------------------------------------
// bf16x3 mma.sync GEMM, CTA tile 128x256, 256 threads, warp tile 64x64,
// BK=32, 4-stage cp.async pipeline with lookahead-2 and ONE barrier/stage.
// C[i,j] = sum_k (Ah+Al)[i,k]*(Bh+Bl)[j,k].
// Output fp32 OR bf16 hi/lo planes. Optional fused bias + 64-chunk softmax.
// ---------------------------------------------------------------------------
#define BM 128
#define BN 256
#define BK 32
#define TA_BYTES (BM * 64)                       // 8192
#define TB_BYTES (BN * 64)                       // 16384
#define STG_BYTES (2 * TA_BYTES + 2 * TB_BYTES)  // 49152
#define NPIPE 4
#define GSMEM (NPIPE * STG_BYTES)                // 196608

__device__ __forceinline__ uint32_t swz(uint32_t row, uint32_t c) {
    return row * 64u + ((c ^ ((row >> 1) & 3u)) << 4);
}

__global__ __launch_bounds__(256, 1)
void mma_gemm(const __nv_bfloat16* __restrict__ aHi,
              const __nv_bfloat16* __restrict__ bHi,
              const float* __restrict__ bias,
              float* __restrict__ cF32,
              __nv_bfloat16* __restrict__ cHi,
              int Kdim, int ldc,
              size_t aPS, size_t bPS, size_t cPS,   // hi->lo plane strides
              size_t aStride, size_t bStride, size_t cStride,  // batch strides
              int do_softmax, float scale)
{
    extern __shared__ char smem[];
    const uint32_t sbase = smem_u32(smem);
    const int tid  = threadIdx.x;
    const int wid  = tid >> 5;
    const int lane = tid & 31;
    const int warp_m = wid & 1;          // 2 warps over M (64 rows each)
    const int warp_n = wid >> 1;         // 4 warps over N (64 cols each)
    const int rowBase = blockIdx.y * BM;
    const int colBase = blockIdx.x * BN;
    const int z = blockIdx.z;

    aHi += (size_t)z * aStride;
    bHi += (size_t)z * bStride;

    // ---- loader setup: 4 A-chunks + 8 B-chunks per thread per stage -----
    uint32_t goffA[4], sdstA[4];
    uint32_t goffB[8], sdstB[8];
#pragma unroll
    for (int i = 0; i < 4; ++i) {
        int q = i * 256 + tid;           // 0..1023
        int plane = q >> 9;
        int w = q & 511;
        int row = w >> 2, c = w & 3;
        goffA[i] = (uint32_t)(plane * aPS + (size_t)(rowBase + row) * Kdim + c * 8);
        sdstA[i] = (uint32_t)(plane * TA_BYTES) + swz((uint32_t)row, (uint32_t)c);
    }
#pragma unroll
    for (int i = 0; i < 8; ++i) {
        int q = i * 256 + tid;           // 0..2047
        int plane = q >> 10;
        int w = q & 1023;
        int row = w >> 2, c = w & 3;
        goffB[i] = (uint32_t)(plane * bPS + (size_t)(colBase + row) * Kdim + c * 8);
        sdstB[i] = (uint32_t)(2 * TA_BYTES + plane * TB_BYTES) + swz((uint32_t)row, (uint32_t)c);
    }

    const int nstage = Kdim / BK;

    // prologue: stages 0 and 1 into bufs 0 and 1
#pragma unroll
    for (int s = 0; s < 2; ++s) {
        uint32_t sb = sbase + s * STG_BYTES;
        const int koff = s * BK;
#pragma unroll
        for (int i = 0; i < 4; ++i) CPA16(sb + sdstA[i], aHi + goffA[i] + koff);
#pragma unroll
        for (int i = 0; i < 8; ++i) CPA16(sb + sdstB[i], bHi + goffB[i] + koff);
        CPCOMMIT();
    }

    // ---- fragment smem offsets (within a plane-tile) --------------------
    uint32_t aoff[4][2], boff[4][2];
#pragma unroll
    for (int m = 0; m < 4; ++m) {
        uint32_t arow = warp_m * 64 + m * 16 + (lane & 7) + ((lane >> 3) & 1) * 8;
#pragma unroll
        for (int ks = 0; ks < 2; ++ks)
            aoff[m][ks] = swz(arow, 2 * ks + (lane >> 4));
    }
#pragma unroll
    for (int p = 0; p < 4; ++p) {
        uint32_t brow = warp_n * 64 + p * 16 + (lane & 7) + ((lane >= 16) ? 8 : 0);
#pragma unroll
        for (int ks = 0; ks < 2; ++ks)
            boff[p][ks] = swz(brow, 2 * ks + ((lane >> 3) & 1));
    }

    float acc[4][8][4];
#pragma unroll
    for (int m = 0; m < 4; ++m)
#pragma unroll
        for (int n = 0; n < 8; ++n)
#pragma unroll
            for (int r = 0; r < 4; ++r) acc[m][n][r] = 0.0f;

    // ---- main loop: load s+2 into buf (s+2)%4, compute buf s%4 ----------
    // Single barrier per stage is safe: max warp skew is 1 iteration
    // (barrier-enforced), and writer buffer (s+3)%4 never equals a
    // laggard's compute buffer s%4.
    for (int s = 0; s < nstage; ++s) {
        if (s + 2 < nstage) {
            uint32_t sb = sbase + ((s + 2) & 3) * STG_BYTES;
            const int koff = (s + 2) * BK;
#pragma unroll
            for (int i = 0; i < 4; ++i) CPA16(sb + sdstA[i], aHi + goffA[i] + koff);
#pragma unroll
            for (int i = 0; i < 8; ++i) CPA16(sb + sdstB[i], bHi + goffB[i] + koff);
        }
        CPCOMMIT();
        CPWAIT2();            // stage s complete (2 newer groups may be in flight)
        __syncthreads();

        const uint32_t sb = sbase + (s & 3) * STG_BYTES;
#pragma unroll
        for (int ks = 0; ks < 2; ++ks) {
            uint32_t ah[4][4], al[4][4];
#pragma unroll
            for (int m = 0; m < 4; ++m) {
                LDSM4(ah[m], sb + aoff[m][ks]);
                LDSM4(al[m], sb + TA_BYTES + aoff[m][ks]);
            }
#pragma unroll
            for (int p = 0; p < 4; ++p) {
                uint32_t bh[4], bl[4];
                LDSM4(bh, sb + 2 * TA_BYTES + boff[p][ks]);
                LDSM4(bl, sb + 2 * TA_BYTES + TB_BYTES + boff[p][ks]);
#pragma unroll
                for (int m = 0; m < 4; ++m) {
#pragma unroll
                    for (int q = 0; q < 2; ++q) {
                        float* a4 = acc[m][2 * p + q];
                        MMA16816(a4, ah[m], bh[2 * q], bh[2 * q + 1]);
                        MMA16816(a4, ah[m], bl[2 * q], bl[2 * q + 1]);
                        MMA16816(a4, al[m], bh[2 * q], bh[2 * q + 1]);
                    }
                }
            }
        }
        // no trailing barrier (see note above)
    }

    // ---- epilogue -------------------------------------------------------
    const int r0 = rowBase + warp_m * 64 + (lane >> 2);
    const int c0 = colBase + warp_n * 64 + (lane & 3) * 2;

    if (bias) {
#pragma unroll
        for (int n = 0; n < 8; ++n) {
            float2 bv = *(const float2*)(bias + c0 + n * 8);
#pragma unroll
            for (int m = 0; m < 4; ++m) {
                acc[m][n][0] += bv.x; acc[m][n][1] += bv.y;
                acc[m][n][2] += bv.x; acc[m][n][3] += bv.y;
            }
        }
    }
    if (do_softmax) {
#pragma unroll
        for (int m = 0; m < 4; ++m) {
#pragma unroll
            for (int hf = 0; hf < 2; ++hf) {
                float mx = -1e30f;
#pragma unroll
                for (int n = 0; n < 8; ++n)
                    mx = fmaxf(mx, fmaxf(acc[m][n][2 * hf], acc[m][n][2 * hf + 1]));
                mx = fmaxf(mx, __shfl_xor_sync(0xffffffffu, mx, 1));
                mx = fmaxf(mx, __shfl_xor_sync(0xffffffffu, mx, 2));
                float sum = 0.0f;
#pragma unroll
                for (int n = 0; n < 8; ++n) {
                    float e0 = __expf(acc[m][n][2 * hf] - mx);
                    float e1 = __expf(acc[m][n][2 * hf + 1] - mx);
                    acc[m][n][2 * hf] = e0; acc[m][n][2 * hf + 1] = e1;
                    sum += e0 + e1;
                }
                sum += __shfl_xor_sync(0xffffffffu, sum, 1);
                sum += __shfl_xor_sync(0xffffffffu, sum, 2);
                float inv = scale / sum;
#pragma unroll
                for (int n = 0; n < 8; ++n) {
                    acc[m][n][2 * hf] *= inv; acc[m][n][2 * hf + 1] *= inv;
                }
            }
        }
    }

    if (cF32) {
        float* Cb = cF32 + (size_t)z * cStride;
#pragma unroll
        for (int m = 0; m < 4; ++m) {
            const int rA = r0 + m * 16, rB = rA + 8;
#pragma unroll
            for (int n = 0; n < 8; ++n) {
                float2 v01; v01.x = acc[m][n][0]; v01.y = acc[m][n][1];
                float2 v23; v23.x = acc[m][n][2]; v23.y = acc[m][n][3];
                *(float2*)(Cb + (size_t)rA * ldc + c0 + n * 8) = v01;
                *(float2*)(Cb + (size_t)rB * ldc + c0 + n * 8) = v23;
            }
        }
    } else {
        __nv_bfloat16* Hb = cHi + (size_t)z * cStride;
        __nv_bfloat16* Lb = cHi + cPS + (size_t)z * cStride;
#pragma unroll
        for (int m = 0; m < 4; ++m) {
            const int rA = r0 + m * 16, rB = rA + 8;
#pragma unroll
            for (int n = 0; n < 8; ++n) {
                uint16_t h0,l0,h1,l1;
                split1(acc[m][n][0], h0, l0);
                split1(acc[m][n][1], h1, l1);
                *(uint32_t*)(Hb + (size_t)rA * ldc + c0 + n * 8) =
                    (uint32_t)h0 | ((uint32_t)h1 << 16);
                *(uint32_t*)(Lb + (size_t)rA * ldc + c0 + n * 8) =
                    (uint32_t)l0 | ((uint32_t)l1 << 16);
                split1(acc[m][n][2], h0, l0);
                split1(acc[m][n][3], h1, l1);
                *(uint32_t*)(Hb + (size_t)rB * ldc + c0 + n * 8) =
                    (uint32_t)h0 | ((uint32_t)h1 << 16);
                *(uint32_t*)(Lb + (size_t)rB * ldc + c0 + n * 8) =
                    (uint32_t)l0 | ((uint32_t)l1 << 16);
            }
        }
    }
}

// ---------------------------------------------------------------------------
// ctx[bh][d][e] = softmax_d( P[b][h64+d,:]·Wv[h64+e,:] + u_d bv_e + bk_d w_e
//                             + N bk_d bv_e ) * scale
// ---------------------------------------------------------------------------
__global__ __launch_bounds__(256)
void ctx_kernel(const float* __restrict__ P, const float* __restrict__ Wv,
                const float* __restrict__ bk, const float* __restrict__ bv,
                const float* __restrict__ u, const float* __restrict__ w,
                float* __restrict__ ctx, float scale)
{
    __shared__ float Ps[64][33];
    __shared__ float Ws[64][33];
    __shared__ float Cm[64][65];

    const int bh = blockIdx.x;
    const int b  = bh >> 4;
    const int h  = bh & 15;
    const float* Pb  = P  + (size_t)b * DD_ + (size_t)(h * 64) * D_;
    const float* Wvb = Wv + (size_t)(h * 64) * D_;

    const int tid = threadIdx.x;
    const int dt = (tid >> 4) * 4;
    const int et = (tid & 15) * 4;
    const int lrow = tid >> 2;
    const int lc   = (tid & 3) * 8;

    float acc[4][4];
#pragma unroll
    for (int i = 0; i < 4; i++)
#pragma unroll
        for (int j = 0; j < 4; j++) acc[i][j] = 0.0f;

    for (int c0 = 0; c0 < D_; c0 += 32) {
#pragma unroll
        for (int i = 0; i < 8; ++i) {
            Ps[lrow][lc + i] = Pb [(size_t)lrow * D_ + c0 + lc + i];
            Ws[lrow][lc + i] = Wvb[(size_t)lrow * D_ + c0 + lc + i];
        }
        __syncthreads();
#pragma unroll 8
        for (int cc = 0; cc < 32; ++cc) {
            float pd[4], we[4];
#pragma unroll
            for (int i = 0; i < 4; ++i) pd[i] = Ps[dt + i][cc];
#pragma unroll
            for (int j = 0; j < 4; ++j) we[j] = Ws[et + j][cc];
#pragma unroll
            for (int i = 0; i < 4; ++i)
#pragma unroll
                for (int j = 0; j < 4; ++j)
                    acc[i][j] = fmaf(pd[i], we[j], acc[i][j]);
        }
        __syncthreads();
    }

    {
        float bkd[4], ud[4], bve[4], wze[4];
#pragma unroll
        for (int i = 0; i < 4; ++i) {
            bkd[i] = bk[h * 64 + dt + i];
            ud[i]  = u [b * D_ + h * 64 + dt + i];
        }
#pragma unroll
        for (int j = 0; j < 4; ++j) {
            bve[j] = bv[h * 64 + et + j];
            wze[j] = w [b * D_ + h * 64 + et + j];
        }
#pragma unroll
        for (int i = 0; i < 4; ++i)
#pragma unroll
            for (int j = 0; j < 4; ++j)
                acc[i][j] += ud[i] * bve[j] + bkd[i] * wze[j]
                           + (float)N_ * bkd[i] * bve[j];
    }

#pragma unroll
    for (int i = 0; i < 4; i++)
#pragma unroll
        for (int j = 0; j < 4; j++)
            Cm[dt + i][et + j] = acc[i][j];
    __syncthreads();

    if (tid < 64) {
        float m = -1e30f;
#pragma unroll 8
        for (int d = 0; d < 64; d++) m = fmaxf(m, Cm[d][tid]);
        float s = 0.0f;
#pragma unroll 8
        for (int d = 0; d < 64; d++) {
            float e = __expf(Cm[d][tid] - m);
            Cm[d][tid] = e;
            s += e;
        }
        float inv = scale / s;
        float* outp = ctx + (size_t)bh * (DH_ * DH_);
#pragma unroll 8
        for (int d = 0; d < 64; d++)
            outp[d * 64 + tid] = Cm[d][tid] * inv;
    }
}

// ---------------------------------------------------------------------------
// Vt[b][r][h64+d] = sum_e Wo[r][h64+e] * ctx[bh][d][e]  -> bf16 hi/lo planes
// ---------------------------------------------------------------------------
__global__ __launch_bounds__(256)
void vt_kernel(const float* __restrict__ ctx, const float* __restrict__ Wo,
               __nv_bfloat16* __restrict__ vtHi, __nv_bfloat16* __restrict__ vtLo)
{
    __shared__ float Cs[64][65];
    __shared__ float Wos[64][65];

    const int bh = blockIdx.x;
    const int b  = bh >> 4;
    const int h  = bh & 15;
    const int r0 = blockIdx.y * 64;
    const int tid = threadIdx.x;

    {
        int d  = tid >> 2;
        int e0 = (tid & 3) * 16;
        const float* src = ctx + (size_t)bh * 4096 + (size_t)d * 64 + e0;
#pragma unroll
        for (int i = 0; i < 16; ++i) Cs[d][e0 + i] = src[i];
        int lr = tid >> 2;
        int c0 = (tid & 3) * 16;
        const float* ws = Wo + (size_t)(r0 + lr) * D_ + h * 64 + c0;
#pragma unroll
        for (int i = 0; i < 16; ++i) Wos[lr][c0 + i] = ws[i];
    }
    __syncthreads();

    const int rl = tid >> 2;
    const int dq = tid & 3;
    float acc[16];
#pragma unroll
    for (int d = 0; d < 16; ++d) acc[d] = 0.0f;

#pragma unroll 8
    for (int e = 0; e < 64; ++e) {
        float wo = Wos[rl][e];
#pragma unroll
        for (int d = 0; d < 16; ++d)
            acc[d] = fmaf(wo, Cs[dq * 16 + d][e], acc[d]);
    }

    size_t base = ((size_t)(b * D_ + r0 + rl)) * D_ + h * 64 + dq * 16;
#pragma unroll
    for (int d = 0; d < 16; d += 2) {
        uint16_t h0,l0,h1,l1;
        split1(acc[d],     h0, l0);
        split1(acc[d + 1], h1, l1);
        *(uint32_t*)(vtHi + base + d) = (uint32_t)h0 | ((uint32_t)h1 << 16);
        *(uint32_t*)(vtLo + base + d) = (uint32_t)l0 | ((uint32_t)l1 << 16);
    }
}

// ---------------------------------------------------------------------------
// Launch. NOTE: launch order is chosen so the 6th kernel launch is the
// Q-projection mma_gemm (ncu capture uses -s 5 -c 1).
// ---------------------------------------------------------------------------
extern "C" void kernel_launch(void* const* d_in, const int* in_sizes, int n_in,
                              void* d_out, int out_size)
{
    const float* q  = (const float*)d_in[0];
    const float* k  = (const float*)d_in[1];
    const float* v  = (const float*)d_in[2];
    const float* Wq = (const float*)d_in[3];
    const float* bq = (const float*)d_in[4];
    const float* Wk = (const float*)d_in[5];
    const float* bk = (const float*)d_in[6];
    const float* Wv = (const float*)d_in[7];
    const float* bv = (const float*)d_in[8];
    const float* Wo = (const float*)d_in[9];
    float* out = (float*)d_out;

    void *p_qpl, *p_qspl, *p_xkT, *p_xvT, *p_gpl, *p_wpl, *p_vtpl,
         *p_P, *p_ctx, *p_spk, *p_spv, *p_sk, *p_sv, *p_u, *p_w;
    cudaGetSymbolAddress(&p_qpl,  g_qpl);
    cudaGetSymbolAddress(&p_qspl, g_qspl);
    cudaGetSymbolAddress(&p_xkT,  g_xkT);
    cudaGetSymbolAddress(&p_xvT,  g_xvT);
    cudaGetSymbolAddress(&p_gpl,  g_gpl);
    cudaGetSymbolAddress(&p_wpl,  g_wpl);
    cudaGetSymbolAddress(&p_vtpl, g_vtpl);
    cudaGetSymbolAddress(&p_P,    g_P);
    cudaGetSymbolAddress(&p_ctx,  g_ctxm);
    cudaGetSymbolAddress(&p_spk,  g_spk);
    cudaGetSymbolAddress(&p_spv,  g_spv);
    cudaGetSymbolAddress(&p_sk,   g_sk);
    cudaGetSymbolAddress(&p_sv,   g_sv);
    cudaGetSymbolAddress(&p_u,    g_u);
    cudaGetSymbolAddress(&p_w,    g_w);
    __nv_bfloat16* qpl  = (__nv_bfloat16*)p_qpl;
    __nv_bfloat16* qspl = (__nv_bfloat16*)p_qspl;
    __nv_bfloat16* xkT  = (__nv_bfloat16*)p_xkT;
    __nv_bfloat16* xvT  = (__nv_bfloat16*)p_xvT;
    __nv_bfloat16* gpl  = (__nv_bfloat16*)p_gpl;
    __nv_bfloat16* wpl  = (__nv_bfloat16*)p_wpl;
    __nv_bfloat16* vtpl = (__nv_bfloat16*)p_vtpl;
    float* Pm   = (float*)p_P;
    float* ctxm = (float*)p_ctx;
    float* spk  = (float*)p_spk;
    float* spv  = (float*)p_spv;
    float* sk   = (float*)p_sk;
    float* sv   = (float*)p_sv;
    float* uu   = (float*)p_u;
    float* ww   = (float*)p_w;

    const float inv_qtr = 0.5946035575013605f;   // 8^(-1/4)

    static int smem_set = 0;
    if (!smem_set) {
        cudaFuncSetAttribute(mma_gemm, cudaFuncAttributeMaxDynamicSharedMemorySize, GSMEM);
        smem_set = 1;
    }

    // [1..3] row-major splits
    split_kernel<<<512, 256>>>(Wq, wpl, wpl + DD_, (int)(DD_ / 4));
    split_kernel<<<512, 256>>>(Wk, wpl + 2 * DD_, wpl + 3 * DD_, (int)(DD_ / 4));
    split_kernel<<<2048, 256>>>(q, qpl, qpl + MD_, (int)(MD_ / 4));
    // [4..5] transposing splits
    {
        dim3 tg(N_ / 32, D_ / 32, B_);
        splitT_kernel<<<tg, 256>>>(k, xkT, xkT + MD_);
        splitT_kernel<<<tg, 256>>>(v, xvT, xvT + MD_);
    }

    // [6] Q projection + fused feature softmax -> qs bf16 planes  (ncu target)
    mma_gemm<<<dim3(D_ / BN, M_ / BM, 1), 256, GSMEM>>>(
        qpl, wpl, bq, nullptr, qspl,
        D_, D_, MD_, DD_, MD_, 0, 0, MD_, 1, inv_qtr);

    // [7..12] column stats for analytic bias terms (no atomics, no memsets)
    colstat_k<<<dim3(B_, 16), 256>>>(k, spk);
    colstat_k<<<dim3(B_, 16), 256>>>(v, spv);
    sreduce_k<<<B_, 256>>>(spk, sk);
    sreduce_k<<<B_, 256>>>(spv, sv);
    matvec_k<<<dim3(B_, 128), 256>>>(Wk, sk, uu);
    matvec_k<<<dim3(B_, 128), 256>>>(Wv, sv, ww);

    // [13] Gram: G'[b] = Xv_b^T Xk_b  -> bf16 planes
    mma_gemm<<<dim3(D_ / BN, D_ / BM, B_), 256, GSMEM>>>(
        xvT, xkT, nullptr, nullptr, gpl,
        N_, D_, MD_, MD_, 4 * DD_,
        (size_t)D_ * N_, (size_t)D_ * N_, DD_, 0, 0.0f);

    // [14] P[b] = Wk (.) G'[b]  -> fp32
    mma_gemm<<<dim3(D_ / BN, D_ / BM, B_), 256, GSMEM>>>(
        wpl + 2 * DD_, gpl, nullptr, Pm, nullptr,
        D_, D_, DD_, 4 * DD_, 0, 0, DD_, DD_, 0, 0.0f);

    // [15] ctx (per b,h): P·Wv^T + bias terms, softmax over d, * scale
    ctx_kernel<<<B_ * H_, 256>>>(Pm, Wv, bk, bv, uu, ww, ctxm, inv_qtr);

    // [16] Vt planes
    vt_kernel<<<dim3(B_ * H_, 16), 256>>>(ctxm, Wo, vtpl, vtpl + 4 * DD_);

    // [17] out[b] = qs_b (.) Vt_b
    mma_gemm<<<dim3(D_ / BN, N_ / BM, B_), 256, GSMEM>>>(
        qspl, vtpl, nullptr, out, nullptr,
        D_, D_, MD_, 4 * DD_, 0,
        (size_t)N_ * D_, DD_, (size_t)N_ * D_, 0, 0.0f);
}